// round 10
// baseline (speedup 1.0000x reference)
#include <cuda_runtime.h>
#include <cstdint>

// Problem constants (fixed shapes per reference)
#define B_   2
#define N_   16384
#define S_   4096        // npoint
#define C_   64
#define NS_  32          // nsample
#define NCID (B_*S_)     // 8192 centroids total

// Scratch (static __device__ arrays: allocation-free per harness rules)
__device__ float g_F1[(size_t)B_ * N_ * 64];   // feats@W1[3:] + b1, [b][n][64]  (8MB)
__device__ int   g_idx[NCID * NS_];            // ball query result               (1MB)

// ---------------------------------------------------------------------------
// Packed fp32x2 helpers (Blackwell FFMA2 — only reachable via PTX)
// ---------------------------------------------------------------------------
__device__ __forceinline__ unsigned long long ffma2(unsigned long long a,
                                                    unsigned long long b,
                                                    unsigned long long c) {
    unsigned long long d;
    asm("fma.rn.f32x2 %0, %1, %2, %3;" : "=l"(d) : "l"(a), "l"(b), "l"(c));
    return d;
}
__device__ __forceinline__ unsigned long long splat2(float a) {
    unsigned long long d;
    asm("mov.b64 %0, {%1, %1};" : "=l"(d) : "f"(a));
    return d;
}
__device__ __forceinline__ void unpack2(unsigned long long p, float& lo, float& hi) {
    unsigned l, h;
    asm("mov.b64 {%0, %1}, %2;" : "=r"(l), "=r"(h) : "l"(p));
    lo = __uint_as_float(l); hi = __uint_as_float(h);
}

// ---------------------------------------------------------------------------
// Kernel 1: F1[b][n][j] = sum_c feats[b][c][n] * W1[3+c][j] + b1[j]
// grid (N/64, B), 256 threads
// ---------------------------------------------------------------------------
__global__ void k_f1(const float* __restrict__ feats,
                     const float* __restrict__ W1,
                     const float* __restrict__ b1) {
    __shared__ float sF[64 * 64];   // [c][n_local]
    __shared__ float sW[64 * 64];   // [c][j]
    __shared__ float sb[64];
    int b  = blockIdx.y;
    int n0 = blockIdx.x * 64;
    int tid = threadIdx.x;

    for (int i = tid; i < 4096; i += 256) sW[i] = W1[192 + i];  // rows 3..66
    if (tid < 64) sb[tid] = b1[tid];
    const float* fb = feats + (size_t)b * 64 * N_;
    for (int i = tid; i < 4096; i += 256) {
        int c = i >> 6, nn = i & 63;
        sF[c * 64 + nn] = fb[(size_t)c * N_ + n0 + nn];
    }
    __syncthreads();

    int n  = tid & 63;
    int j0 = (tid >> 6) * 16;
    float acc[16];
#pragma unroll
    for (int j = 0; j < 16; j++) acc[j] = sb[j0 + j];
#pragma unroll 8
    for (int c = 0; c < 64; c++) {
        float f = sF[c * 64 + n];
#pragma unroll
        for (int j = 0; j < 16; j++) acc[j] += f * sW[c * 64 + j0 + j];
    }
    float* dst = g_F1 + ((size_t)b * N_ + n0 + n) * 64 + j0;
#pragma unroll
    for (int j = 0; j < 16; j += 4) {
        float4 v = make_float4(acc[j], acc[j+1], acc[j+2], acc[j+3]);
        *(float4*)(dst + j) = v;
    }
}

// ---------------------------------------------------------------------------
// Kernel 2: ball query. One warp per centroid, 8 warps/block, smem point tiles.
// ---------------------------------------------------------------------------
__global__ void k_bq(const float* __restrict__ xyz) {
    const int TILE = 2048;
    __shared__ float spx[TILE], spy[TILE], spz[TILE], sn2[TILE];
    __shared__ int s_done;
    int tid  = threadIdx.x;
    int lane = tid & 31, w = tid >> 5;
    int cid  = blockIdx.x * 8 + w;
    int b = cid >> 12, s = cid & (S_ - 1);
    if (tid == 0) s_done = 0;

    const float* xb = xyz + (size_t)b * N_ * 3;
    float cx = xb[s*3], cy = xb[s*3+1], cz = xb[s*3+2];
    float cn2 = cx*cx + cy*cy + cz*cz;
    const float R2 = 0.4f * 0.4f;

    int  cnt = 0, firstn = 0;
    bool flagged = false;
    int* myidx = g_idx + cid * NS_;

    for (int t0 = 0; t0 < N_; t0 += TILE) {
        for (int i = tid; i < TILE; i += 256) {
            float x = xb[(t0+i)*3], y = xb[(t0+i)*3+1], z = xb[(t0+i)*3+2];
            spx[i] = x; spy[i] = y; spz[i] = z; sn2[i] = x*x + y*y + z*z;
        }
        __syncthreads();
        if (cnt < NS_) {
            for (int it = 0; it < TILE/32; it++) {
                int j = it*32 + lane;
                float d2 = cn2 + sn2[j] - 2.0f*(cx*spx[j] + cy*spy[j] + cz*spz[j]);
                bool hit = d2 < R2;
                unsigned mask = __ballot_sync(0xffffffffu, hit);
                if (mask) {
                    if (cnt == 0) firstn = t0 + it*32 + (__ffs(mask) - 1);
                    int pos = cnt + __popc(mask & ((1u << lane) - 1u));
                    if (hit && pos < NS_) myidx[pos] = t0 + j;
                    cnt += __popc(mask);
                    if (cnt >= NS_) break;
                }
            }
            if (cnt >= NS_ && !flagged) {
                flagged = true;
                if (lane == 0) atomicAdd(&s_done, 1);
            }
        }
        __syncthreads();
        if (s_done == 8) break;
    }
    if (cnt < NS_) {
        int fv = (cnt > 0) ? firstn : 0;
        if (lane < NS_ - cnt) myidx[cnt + lane] = fv;
    }
}

// ---------------------------------------------------------------------------
// Kernel 3: fused MLP + max-pool — outer-product form, broadcast weights.
// Activations in [k][n] (conflict-free scalar LDS per lane), weights in
// natural [k][c] (warp-broadcast LDS.128, crossbar-free), FFMA2 packed
// along c with bias pre-folded into the accumulators.
// ---------------------------------------------------------------------------
__global__ __launch_bounds__(128, 3)
void k_mlp(const float* __restrict__ xyz,
           const float* __restrict__ W1, const float* __restrict__ W2,
           const float* __restrict__ b2, const float* __restrict__ W3,
           const float* __restrict__ b3, float* __restrict__ outf) {
    extern __shared__ float sm[];
    float* sW2  = sm;            // [k][c] 64x64  (4096)
    float* sW3  = sm + 4096;     // [k][c] 64x128 (8192)
    float* sW1x = sm + 12288;    // 3*64
    float* sb2  = sm + 12480;    // 64
    float* sb3  = sm + 12544;    // 128
    float* hbuf = sm + 12672;    // 4352 floats, overlaid buffers
    float* h1T  = hbuf;          // [k][n] 64x32
    float* h2T  = hbuf + 2048;   // [k][n] 64x32
    float* h3   = hbuf;          // [c][n] stride 33, 128 rows (overlays h1T+h2T)
    int tid  = threadIdx.x;
    int lane = tid & 31, w = tid >> 5;

    for (int i = tid; i < 4096; i += 128) sW2[i] = W2[i];
    for (int i = tid; i < 8192; i += 128) sW3[i] = W3[i];
    if (tid < 64) {
        sW1x[tid] = W1[tid]; sW1x[64+tid] = W1[64+tid]; sW1x[128+tid] = W1[128+tid];
        sb2[tid] = b2[tid];
    }
    sb3[tid] = b3[tid];
    __syncthreads();

    int j0 = w * 16;   // layer-1 j-range
    int c2 = w * 16;   // layer-2 c-tile base (4 warps x 16 = 64)
    int c3 = w * 32;   // layer-3 c-tile base (4 warps x 32 = 128)

    for (int ci = 0; ci < 8; ci++) {
        int cid = blockIdx.x * 8 + ci;
        int b = cid >> 12, s = cid & (S_ - 1);

        // ---- layer 1: h1[j][n] = relu(F1[idx[n]][j] + dxyz . W1xyz[:,j]) ----
        {
            int pidx = g_idx[cid * NS_ + lane];
            const float* xb = xyz + (size_t)b * N_ * 3;
            float dx = xb[pidx*3+0] - xb[s*3+0];
            float dy = xb[pidx*3+1] - xb[s*3+1];
            float dz = xb[pidx*3+2] - xb[s*3+2];
            const float* f1p = g_F1 + ((size_t)b * N_ + pidx) * 64 + j0;
#pragma unroll
            for (int q = 0; q < 4; q++) {
                float4 f = *(const float4*)(f1p + q*4);
                int j = j0 + q*4;
                h1T[(j+0)*32+lane] = fmaxf(f.x + dx*sW1x[j+0] + dy*sW1x[64+j+0] + dz*sW1x[128+j+0], 0.f);
                h1T[(j+1)*32+lane] = fmaxf(f.y + dx*sW1x[j+1] + dy*sW1x[64+j+1] + dz*sW1x[128+j+1], 0.f);
                h1T[(j+2)*32+lane] = fmaxf(f.z + dx*sW1x[j+2] + dy*sW1x[64+j+2] + dz*sW1x[128+j+2], 0.f);
                h1T[(j+3)*32+lane] = fmaxf(f.w + dx*sW1x[j+3] + dy*sW1x[64+j+3] + dz*sW1x[128+j+3], 0.f);
            }
        }
        __syncthreads();

        // ---- layer 2: h2[c][n] = relu(b2[c] + sum_k h1[k][n] W2[k][c]) ----
        {
            unsigned long long acc[8];
            {
                const ulonglong2* bp = (const ulonglong2*)(sb2 + c2);
#pragma unroll
                for (int q = 0; q < 4; q++) { acc[2*q] = bp[q].x; acc[2*q+1] = bp[q].y; }
            }
#pragma unroll 8
            for (int k = 0; k < 64; k++) {
                unsigned long long ap = splat2(h1T[k*32 + lane]);
                const ulonglong2* wp = (const ulonglong2*)(sW2 + (k << 6) + c2);
                ulonglong2 q0 = wp[0], q1 = wp[1], q2 = wp[2], q3 = wp[3];
                acc[0] = ffma2(ap, q0.x, acc[0]); acc[1] = ffma2(ap, q0.y, acc[1]);
                acc[2] = ffma2(ap, q1.x, acc[2]); acc[3] = ffma2(ap, q1.y, acc[3]);
                acc[4] = ffma2(ap, q2.x, acc[4]); acc[5] = ffma2(ap, q2.y, acc[5]);
                acc[6] = ffma2(ap, q3.x, acc[6]); acc[7] = ffma2(ap, q3.y, acc[7]);
            }
#pragma unroll
            for (int j = 0; j < 8; j++) {
                float lo, hi; unpack2(acc[j], lo, hi);
                h2T[(c2 + 2*j + 0)*32 + lane] = fmaxf(lo, 0.f);
                h2T[(c2 + 2*j + 1)*32 + lane] = fmaxf(hi, 0.f);
            }
        }
        __syncthreads();

        // ---- layer 3: h3[c][n] = relu(b3[c] + sum_k h2[k][n] W3[k][c]) ----
        {
            unsigned long long acc[16];
            {
                const ulonglong2* bp = (const ulonglong2*)(sb3 + c3);
#pragma unroll
                for (int q = 0; q < 8; q++) { acc[2*q] = bp[q].x; acc[2*q+1] = bp[q].y; }
            }
#pragma unroll 8
            for (int k = 0; k < 64; k++) {
                unsigned long long ap = splat2(h2T[k*32 + lane]);
                const ulonglong2* wp = (const ulonglong2*)(sW3 + (k << 7) + c3);
#pragma unroll
                for (int q = 0; q < 8; q++) {
                    ulonglong2 ww = wp[q];
                    acc[2*q]   = ffma2(ap, ww.x, acc[2*q]);
                    acc[2*q+1] = ffma2(ap, ww.y, acc[2*q+1]);
                }
            }
            __syncthreads();   // h2T/h1T dead; safe to overlay h3
#pragma unroll
            for (int j = 0; j < 16; j++) {
                float lo, hi; unpack2(acc[j], lo, hi);
                h3[(c3 + 2*j + 0)*33 + lane] = fmaxf(lo, 0.f);
                h3[(c3 + 2*j + 1)*33 + lane] = fmaxf(hi, 0.f);
            }
        }
        __syncthreads();

        // ---- max over the 32 neighbors: thread tid <-> channel c=tid ----
        {
            const float* row = h3 + tid * 33;
            float mx = row[0];
#pragma unroll
            for (int n = 1; n < 32; n++) mx = fmaxf(mx, row[n]);
            outf[((size_t)b * 128 + tid) * S_ + s] = mx;
        }
        __syncthreads();   // h3 region becomes next centroid's h1T/h2T
    }
}

// ---------------------------------------------------------------------------
// Kernel 4: new_xyz copy + samp_idx (as float values)
// ---------------------------------------------------------------------------
__global__ void k_out(const float* __restrict__ xyz, float* __restrict__ out) {
    int i = blockIdx.x * blockDim.x + threadIdx.x;
    if (i < B_ * S_ * 3) {
        int b = i / (S_ * 3), r = i % (S_ * 3);
        out[i] = xyz[(size_t)b * N_ * 3 + r];
    } else {
        int j = i - B_ * S_ * 3;
        if (j < B_ * S_)
            out[B_*S_*3 + (size_t)B_*128*S_ + j] = (float)(j & (S_ - 1));
    }
}

// ---------------------------------------------------------------------------
extern "C" void kernel_launch(void* const* d_in, const int* in_sizes, int n_in,
                              void* d_out, int out_size) {
    const float* xyz   = (const float*)d_in[0];
    const float* feats = (const float*)d_in[1];
    const float* W1    = (const float*)d_in[2];
    const float* b1    = (const float*)d_in[3];
    const float* W2    = (const float*)d_in[4];
    const float* b2    = (const float*)d_in[5];
    const float* W3    = (const float*)d_in[6];
    const float* b3    = (const float*)d_in[7];
    float* out = (float*)d_out;

    const int NXYZ = B_ * S_ * 3;               // 24576
    const int NFEA = B_ * 128 * S_;             // 1048576
    float* outf = out + NXYZ;                   // features region (full tuple layout)
    bool full_layout = (out_size >= NXYZ + NFEA + B_ * S_);
    if (!full_layout && out_size == NFEA) outf = out;  // features-only fallback

    const size_t smem_mlp = 17024 * sizeof(float);  // 68096 B
    cudaFuncSetAttribute(k_mlp, cudaFuncAttributeMaxDynamicSharedMemorySize,
                         (int)smem_mlp);

    k_f1<<<dim3(N_/64, B_), 256>>>(feats, W1, b1);
    k_bq<<<NCID/8, 256>>>(xyz);
    k_mlp<<<NCID/8, 128, smem_mlp>>>(xyz, W1, W2, b2, W3, b3, outf);
    if (full_layout) {
        int tot = NXYZ + B_ * S_;
        k_out<<<(tot + 255)/256, 256>>>(xyz, out);
    }
}

// round 12
// speedup vs baseline: 1.2747x; 1.2747x over previous
#include <cuda_runtime.h>
#include <cstdint>

// Problem constants (fixed shapes per reference)
#define B_   2
#define N_   16384
#define S_   4096        // npoint
#define C_   64
#define NS_  32          // nsample
#define NCID (B_*S_)     // 8192 centroids total

// Scratch (static __device__ arrays: allocation-free per harness rules)
__device__ float g_F1[(size_t)B_ * N_ * 64];   // feats@W1[3:] + b1, [b][n][64]  (8MB)
__device__ int   g_idx[NCID * NS_];            // ball query result               (1MB)

// ---------------------------------------------------------------------------
// Kernel 1: F1[b][n][j] = sum_c feats[b][c][n] * W1[3+c][j] + b1[j]
// grid (N/64, B), 256 threads
// ---------------------------------------------------------------------------
__global__ void k_f1(const float* __restrict__ feats,
                     const float* __restrict__ W1,
                     const float* __restrict__ b1) {
    __shared__ float sF[64 * 64];   // [c][n_local]
    __shared__ float sW[64 * 64];   // [c][j]
    __shared__ float sb[64];
    int b  = blockIdx.y;
    int n0 = blockIdx.x * 64;
    int tid = threadIdx.x;

    for (int i = tid; i < 4096; i += 256) sW[i] = W1[192 + i];  // rows 3..66
    if (tid < 64) sb[tid] = b1[tid];
    const float* fb = feats + (size_t)b * 64 * N_;
    for (int i = tid; i < 4096; i += 256) {
        int c = i >> 6, nn = i & 63;
        sF[c * 64 + nn] = fb[(size_t)c * N_ + n0 + nn];
    }
    __syncthreads();

    int n  = tid & 63;
    int j0 = (tid >> 6) * 16;
    float acc[16];
#pragma unroll
    for (int j = 0; j < 16; j++) acc[j] = sb[j0 + j];
#pragma unroll 8
    for (int c = 0; c < 64; c++) {
        float f = sF[c * 64 + n];
#pragma unroll
        for (int j = 0; j < 16; j++) acc[j] += f * sW[c * 64 + j0 + j];
    }
    float* dst = g_F1 + ((size_t)b * N_ + n0 + n) * 64 + j0;
#pragma unroll
    for (int j = 0; j < 16; j += 4) {
        float4 v = make_float4(acc[j], acc[j+1], acc[j+2], acc[j+3]);
        *(float4*)(dst + j) = v;
    }
}

// ---------------------------------------------------------------------------
// Kernel 2: ball query. One warp per centroid, 8 warps/block, smem point tiles.
// ---------------------------------------------------------------------------
__global__ void k_bq(const float* __restrict__ xyz) {
    const int TILE = 2048;
    __shared__ float spx[TILE], spy[TILE], spz[TILE], sn2[TILE];
    __shared__ int s_done;
    int tid  = threadIdx.x;
    int lane = tid & 31, w = tid >> 5;
    int cid  = blockIdx.x * 8 + w;
    int b = cid >> 12, s = cid & (S_ - 1);
    if (tid == 0) s_done = 0;

    const float* xb = xyz + (size_t)b * N_ * 3;
    float cx = xb[s*3], cy = xb[s*3+1], cz = xb[s*3+2];
    float cn2 = cx*cx + cy*cy + cz*cz;
    const float R2 = 0.4f * 0.4f;

    int  cnt = 0, firstn = 0;
    bool flagged = false;
    int* myidx = g_idx + cid * NS_;

    for (int t0 = 0; t0 < N_; t0 += TILE) {
        for (int i = tid; i < TILE; i += 256) {
            float x = xb[(t0+i)*3], y = xb[(t0+i)*3+1], z = xb[(t0+i)*3+2];
            spx[i] = x; spy[i] = y; spz[i] = z; sn2[i] = x*x + y*y + z*z;
        }
        __syncthreads();
        if (cnt < NS_) {
            for (int it = 0; it < TILE/32; it++) {
                int j = it*32 + lane;
                float d2 = cn2 + sn2[j] - 2.0f*(cx*spx[j] + cy*spy[j] + cz*spz[j]);
                bool hit = d2 < R2;
                unsigned mask = __ballot_sync(0xffffffffu, hit);
                if (mask) {
                    if (cnt == 0) firstn = t0 + it*32 + (__ffs(mask) - 1);
                    int pos = cnt + __popc(mask & ((1u << lane) - 1u));
                    if (hit && pos < NS_) myidx[pos] = t0 + j;
                    cnt += __popc(mask);
                    if (cnt >= NS_) break;
                }
            }
            if (cnt >= NS_ && !flagged) {
                flagged = true;
                if (lane == 0) atomicAdd(&s_done, 1);
            }
        }
        __syncthreads();
        if (s_done == 8) break;
    }
    if (cnt < NS_) {
        int fv = (cnt > 0) ? firstn : 0;
        if (lane < NS_ - cnt) myidx[cnt + lane] = fv;
    }
}

// ---------------------------------------------------------------------------
// Kernel 3: fused MLP + max-pool. 256 threads = 2 centroids in parallel
// (threads 0-127 -> centroid A, 128-255 -> centroid B), 4 centroids/block.
// Layer-1 gather (g_F1 random rows, L2 ~250cyc) is register-prefetched one
// centroid ahead, hidden behind layer-2/3 compute.
// ---------------------------------------------------------------------------
__global__ __launch_bounds__(256, 2)
void k_mlp(const float* __restrict__ xyz,
           const float* __restrict__ W1, const float* __restrict__ W2,
           const float* __restrict__ b2, const float* __restrict__ W3,
           const float* __restrict__ b3, float* __restrict__ outf) {
    extern __shared__ float sm[];
    float* sW2  = sm;            // 64*64
    float* sW3  = sm + 4096;     // 64*128
    float* sW1x = sm + 12288;    // 3*64
    float* sb2  = sm + 12480;    // 64
    float* sb3  = sm + 12544;    // 128
    float* hbuf = sm + 12672;    // 2 halves x (h1T 2048 + h2T 2048)
    int tid  = threadIdx.x;
    int ht   = tid & 127;        // thread-in-half
    int half = tid >> 7;

    float* h1T = hbuf + half * 4096;        // [k][n] 64x32
    float* h2T = h1T + 2048;                // [k][n] 64x32

    for (int i = tid; i < 4096; i += 256) sW2[i] = W2[i];
    for (int i = tid; i < 8192; i += 256) sW3[i] = W3[i];
    if (tid < 64) { sW1x[tid] = W1[tid]; sW1x[64+tid] = W1[64+tid]; sW1x[128+tid] = W1[128+tid]; }
    if (tid >= 64 && tid < 128) sb2[tid - 64] = b2[tid - 64];
    if (tid >= 128) sb3[tid - 128] = b3[tid - 128];

    // mappings (within a 128-thread half, identical to the R1 layout)
    int n1 = ht & 31;  int j0 = (ht >> 5) * 16;     // layer 1
    int tr = ht & 7;   int n0 = tr * 4;             // layer 2/3 n-tile
    int tcg = ht >> 3; int c2 = tcg * 4; int c3 = tcg * 8;

    // ---- prefetch state (registers) ----
    float  p_dx, p_dy, p_dz;
    float4 p_f[4];
    auto prefetch = [&](int cid) {
        int b = cid >> 12, s = cid & (S_ - 1);
        const float* xb = xyz + (size_t)b * N_ * 3;
        int pidx = g_idx[cid * NS_ + n1];
        p_dx = xb[pidx*3+0] - xb[s*3+0];
        p_dy = xb[pidx*3+1] - xb[s*3+1];
        p_dz = xb[pidx*3+2] - xb[s*3+2];
        const float* f1p = g_F1 + ((size_t)b * N_ + pidx) * 64 + j0;
#pragma unroll
        for (int q = 0; q < 4; q++) p_f[q] = *(const float4*)(f1p + q*4);
    };

    int cid0 = blockIdx.x * 4 + half;   // this half's first centroid
    prefetch(cid0);
    __syncthreads();                    // weights staged + first prefetch issued

    for (int ci = 0; ci < 2; ci++) {
        int cid = cid0 + ci * 2;
        int b = cid >> 12, s = cid & (S_ - 1);

        // ---- layer 1: consume prefetched gather ----
#pragma unroll
        for (int q = 0; q < 4; q++) {
            float4 f = p_f[q];
            int j = j0 + q*4;
            h1T[(j+0)*32+n1] = fmaxf(f.x + p_dx*sW1x[j+0] + p_dy*sW1x[64+j+0] + p_dz*sW1x[128+j+0], 0.f);
            h1T[(j+1)*32+n1] = fmaxf(f.y + p_dx*sW1x[j+1] + p_dy*sW1x[64+j+1] + p_dz*sW1x[128+j+1], 0.f);
            h1T[(j+2)*32+n1] = fmaxf(f.z + p_dx*sW1x[j+2] + p_dy*sW1x[64+j+2] + p_dz*sW1x[128+j+2], 0.f);
            h1T[(j+3)*32+n1] = fmaxf(f.w + p_dx*sW1x[j+3] + p_dy*sW1x[64+j+3] + p_dz*sW1x[128+j+3], 0.f);
        }
        if (ci < 1) prefetch(cid + 2);  // hide next gather behind layers 2+3
        __syncthreads();

        // ---- layer 2: h2[n][c] = relu(b2 + sum_k h1[n][k] W2[k][c]) ----
        {
            float acc[4][4];
#pragma unroll
            for (int j = 0; j < 4; j++) {
                float bv = sb2[c2 + j];
                acc[0][j]=bv; acc[1][j]=bv; acc[2][j]=bv; acc[3][j]=bv;
            }
#pragma unroll 8
            for (int k = 0; k < 64; k++) {
                float4 a = *(const float4*)(h1T + k*32 + n0);
                float4 w = *(const float4*)(sW2 + k*64 + c2);
                acc[0][0] += a.x*w.x; acc[0][1] += a.x*w.y; acc[0][2] += a.x*w.z; acc[0][3] += a.x*w.w;
                acc[1][0] += a.y*w.x; acc[1][1] += a.y*w.y; acc[1][2] += a.y*w.z; acc[1][3] += a.y*w.w;
                acc[2][0] += a.z*w.x; acc[2][1] += a.z*w.y; acc[2][2] += a.z*w.z; acc[2][3] += a.z*w.w;
                acc[3][0] += a.w*w.x; acc[3][1] += a.w*w.y; acc[3][2] += a.w*w.z; acc[3][3] += a.w*w.w;
            }
#pragma unroll
            for (int j = 0; j < 4; j++) {
                float4 v = make_float4(fmaxf(acc[0][j],0.f), fmaxf(acc[1][j],0.f),
                                       fmaxf(acc[2][j],0.f), fmaxf(acc[3][j],0.f));
                *(float4*)(h2T + (c2+j)*32 + n0) = v;
            }
        }
        __syncthreads();

        // ---- layer 3 + relu + max over neighbors ----
        {
            float acc[4][8];
#pragma unroll
            for (int j = 0; j < 8; j++) {
                float bv = sb3[c3 + j];
                acc[0][j]=bv; acc[1][j]=bv; acc[2][j]=bv; acc[3][j]=bv;
            }
#pragma unroll 8
            for (int k = 0; k < 64; k++) {
                float4 a  = *(const float4*)(h2T + k*32 + n0);
                float4 w0 = *(const float4*)(sW3 + k*128 + c3);
                float4 w1 = *(const float4*)(sW3 + k*128 + c3 + 4);
                acc[0][0]+=a.x*w0.x; acc[0][1]+=a.x*w0.y; acc[0][2]+=a.x*w0.z; acc[0][3]+=a.x*w0.w;
                acc[0][4]+=a.x*w1.x; acc[0][5]+=a.x*w1.y; acc[0][6]+=a.x*w1.z; acc[0][7]+=a.x*w1.w;
                acc[1][0]+=a.y*w0.x; acc[1][1]+=a.y*w0.y; acc[1][2]+=a.y*w0.z; acc[1][3]+=a.y*w0.w;
                acc[1][4]+=a.y*w1.x; acc[1][5]+=a.y*w1.y; acc[1][6]+=a.y*w1.z; acc[1][7]+=a.y*w1.w;
                acc[2][0]+=a.z*w0.x; acc[2][1]+=a.z*w0.y; acc[2][2]+=a.z*w0.z; acc[2][3]+=a.z*w0.w;
                acc[2][4]+=a.z*w1.x; acc[2][5]+=a.z*w1.y; acc[2][6]+=a.z*w1.z; acc[2][7]+=a.z*w1.w;
                acc[3][0]+=a.w*w0.x; acc[3][1]+=a.w*w0.y; acc[3][2]+=a.w*w0.z; acc[3][3]+=a.w*w0.w;
                acc[3][4]+=a.w*w1.x; acc[3][5]+=a.w*w1.y; acc[3][6]+=a.w*w1.z; acc[3][7]+=a.w*w1.w;
            }
            float m[8];
#pragma unroll
            for (int j = 0; j < 8; j++)
                m[j] = fmaxf(fmaxf(fmaxf(acc[0][j], acc[1][j]),
                                   fmaxf(acc[2][j], acc[3][j])), 0.f);
#pragma unroll
            for (int off = 1; off < 8; off <<= 1) {
#pragma unroll
                for (int j = 0; j < 8; j++)
                    m[j] = fmaxf(m[j], __shfl_xor_sync(0xffffffffu, m[j], off));
            }
            if (tr == 0) {
                float* o = outf + ((size_t)b * 128 + c3) * S_ + s;
#pragma unroll
                for (int j = 0; j < 8; j++) o[(size_t)j * S_] = m[j];
            }
        }
        __syncthreads();
    }
}

// ---------------------------------------------------------------------------
// Kernel 4: new_xyz copy + samp_idx (as float values)
// ---------------------------------------------------------------------------
__global__ void k_out(const float* __restrict__ xyz, float* __restrict__ out) {
    int i = blockIdx.x * blockDim.x + threadIdx.x;
    if (i < B_ * S_ * 3) {
        int b = i / (S_ * 3), r = i % (S_ * 3);
        out[i] = xyz[(size_t)b * N_ * 3 + r];
    } else {
        int j = i - B_ * S_ * 3;
        if (j < B_ * S_)
            out[B_*S_*3 + (size_t)B_*128*S_ + j] = (float)(j & (S_ - 1));
    }
}

// ---------------------------------------------------------------------------
extern "C" void kernel_launch(void* const* d_in, const int* in_sizes, int n_in,
                              void* d_out, int out_size) {
    const float* xyz   = (const float*)d_in[0];
    const float* feats = (const float*)d_in[1];
    const float* W1    = (const float*)d_in[2];
    const float* b1    = (const float*)d_in[3];
    const float* W2    = (const float*)d_in[4];
    const float* b2    = (const float*)d_in[5];
    const float* W3    = (const float*)d_in[6];
    const float* b3    = (const float*)d_in[7];
    float* out = (float*)d_out;

    const int NXYZ = B_ * S_ * 3;               // 24576
    const int NFEA = B_ * 128 * S_;             // 1048576
    float* outf = out + NXYZ;                   // features region (full tuple layout)
    bool full_layout = (out_size >= NXYZ + NFEA + B_ * S_);
    if (!full_layout && out_size == NFEA) outf = out;  // features-only fallback

    const size_t smem_mlp = 20864 * sizeof(float);  // 83456 B
    cudaFuncSetAttribute(k_mlp, cudaFuncAttributeMaxDynamicSharedMemorySize,
                         (int)smem_mlp);

    // k_out first: independent output regions, and it shifts k_mlp into the
    // launch slot the ncu capture has been hitting (instrumentation).
    if (full_layout) {
        int tot = NXYZ + B_ * S_;
        k_out<<<(tot + 255)/256, 256>>>(xyz, out);
    }
    k_f1<<<dim3(N_/64, B_), 256>>>(feats, W1, b1);
    k_bq<<<NCID/8, 256>>>(xyz);
    k_mlp<<<NCID/4, 256, smem_mlp>>>(xyz, W1, W2, b2, W3, b3, outf);
}

// round 14
// speedup vs baseline: 1.2967x; 1.0172x over previous
#include <cuda_runtime.h>
#include <cstdint>

// Problem constants (fixed shapes per reference)
#define B_   2
#define N_   16384
#define S_   4096        // npoint
#define C_   64
#define NS_  32          // nsample
#define NCID (B_*S_)     // 8192 centroids total

// Scratch (static __device__ arrays: allocation-free per harness rules)
__device__ float  g_F1[(size_t)B_ * N_ * 64];  // feats@W1[3:] + b1, [b][n][64] (8MB)
__device__ int    g_idx[NCID * NS_];           // ball query result              (1MB)
__device__ float4 g_pts[(size_t)B_ * N_];      // packed (x,y,z,|p|^2)          (512KB)

// ---------------------------------------------------------------------------
// Kernel 0: pack points to float4 (x,y,z,n2) + new_xyz copy + samp_idx.
// 32768 threads: i indexes both the pack task and the output task.
// ---------------------------------------------------------------------------
__global__ void k_pack_out(const float* __restrict__ xyz,
                           float* __restrict__ out, int full_layout) {
    int i = blockIdx.x * blockDim.x + threadIdx.x;   // 0 .. 32767
    // pack task
    {
        int b = i >> 14, n = i & (N_ - 1);
        const float* p = xyz + ((size_t)b * N_ + n) * 3;
        float x = p[0], y = p[1], z = p[2];
        g_pts[(size_t)b * N_ + n] = make_float4(x, y, z, x*x + y*y + z*z);
    }
    // output task
    if (full_layout) {
        if (i < B_ * S_ * 3) {
            int b = i / (S_ * 3), r = i % (S_ * 3);
            out[i] = xyz[(size_t)b * N_ * 3 + r];
        } else {
            int j = i - B_ * S_ * 3;                 // 0 .. 8191
            out[B_*S_*3 + (size_t)B_*128*S_ + j] = (float)(j & (S_ - 1));
        }
    }
}

// ---------------------------------------------------------------------------
// Kernel 1: F1[b][n][j] = sum_c feats[b][c][n] * W1[3+c][j] + b1[j]
// grid (N/64, B), 256 threads. Weight reads are warp-uniform LDS.128.
// ---------------------------------------------------------------------------
__global__ void k_f1(const float* __restrict__ feats,
                     const float* __restrict__ W1,
                     const float* __restrict__ b1) {
    __shared__ float sF[64 * 64];   // [c][n_local]
    __shared__ float sW[64 * 64];   // [c][j]
    __shared__ float sb[64];
    int b  = blockIdx.y;
    int n0 = blockIdx.x * 64;
    int tid = threadIdx.x;

    for (int i = tid; i < 4096; i += 256) sW[i] = W1[192 + i];  // rows 3..66
    if (tid < 64) sb[tid] = b1[tid];
    const float* fb = feats + (size_t)b * 64 * N_;
    for (int i = tid; i < 4096; i += 256) {
        int c = i >> 6, nn = i & 63;
        sF[c * 64 + nn] = fb[(size_t)c * N_ + n0 + nn];
    }
    __syncthreads();

    int n  = tid & 63;
    int j0 = (tid >> 6) * 16;       // warp-uniform
    float acc[16];
#pragma unroll
    for (int j = 0; j < 16; j++) acc[j] = sb[j0 + j];
#pragma unroll 8
    for (int c = 0; c < 64; c++) {
        float f = sF[c * 64 + n];
        const float4* wp = (const float4*)(sW + c * 64 + j0);
        float4 w0 = wp[0], w1 = wp[1], w2 = wp[2], w3 = wp[3];
        acc[0]  += f*w0.x; acc[1]  += f*w0.y; acc[2]  += f*w0.z; acc[3]  += f*w0.w;
        acc[4]  += f*w1.x; acc[5]  += f*w1.y; acc[6]  += f*w1.z; acc[7]  += f*w1.w;
        acc[8]  += f*w2.x; acc[9]  += f*w2.y; acc[10] += f*w2.z; acc[11] += f*w2.w;
        acc[12] += f*w3.x; acc[13] += f*w3.y; acc[14] += f*w3.z; acc[15] += f*w3.w;
    }
    float* dst = g_F1 + ((size_t)b * N_ + n0 + n) * 64 + j0;
#pragma unroll
    for (int j = 0; j < 16; j += 4) {
        float4 v = make_float4(acc[j], acc[j+1], acc[j+2], acc[j+3]);
        *(float4*)(dst + j) = v;
    }
}

// ---------------------------------------------------------------------------
// Kernel 2: ball query. One warp per centroid, 8 warps/block.
// Tiles staged as packed float4 (LDG.128 -> STS.128); test = LDS.128 + 3 FMA.
// Semantics identical to prior rounds (first-32 ascending, first-hit fill).
// ---------------------------------------------------------------------------
__global__ void k_bq(const float* __restrict__ xyz) {
    const int TILE = 2048;
    __shared__ float4 sp[TILE];     // 32KB
    __shared__ int s_done;
    int tid  = threadIdx.x;
    int lane = tid & 31, w = tid >> 5;
    int cid  = blockIdx.x * 8 + w;
    int b = cid >> 12, s = cid & (S_ - 1);
    if (tid == 0) s_done = 0;

    const float4* pb = g_pts + (size_t)b * N_;
    float4 cp = pb[s];
    float cx = cp.x, cy = cp.y, cz = cp.z, cn2 = cp.w;
    const float R2 = 0.4f * 0.4f;

    int  cnt = 0, firstn = 0;
    bool flagged = false;
    int* myidx = g_idx + cid * NS_;

    for (int t0 = 0; t0 < N_; t0 += TILE) {
        for (int i = tid; i < TILE; i += 256) sp[i] = pb[t0 + i];
        __syncthreads();
        if (cnt < NS_) {
            for (int it = 0; it < TILE/32; it++) {
                float4 p = sp[it*32 + lane];
                float d2 = cn2 + p.w - 2.0f*(cx*p.x + cy*p.y + cz*p.z);
                bool hit = d2 < R2;
                unsigned mask = __ballot_sync(0xffffffffu, hit);
                if (mask) {
                    if (cnt == 0) firstn = t0 + it*32 + (__ffs(mask) - 1);
                    int pos = cnt + __popc(mask & ((1u << lane) - 1u));
                    if (hit && pos < NS_) myidx[pos] = t0 + it*32 + lane;
                    cnt += __popc(mask);
                    if (cnt >= NS_) break;
                }
            }
            if (cnt >= NS_ && !flagged) {
                flagged = true;
                if (lane == 0) atomicAdd(&s_done, 1);
            }
        }
        __syncthreads();
        if (s_done == 8) break;
    }
    if (cnt < NS_) {
        int fv = (cnt > 0) ? firstn : 0;
        if (lane < NS_ - cnt) myidx[cnt + lane] = fv;
    }
}

// ---------------------------------------------------------------------------
// Kernel 3: fused MLP + max-pool. 256 threads = 2 centroids in parallel
// (threads 0-127 -> centroid A, 128-255 -> centroid B), 4 centroids/block.
// Layer-1 gather (g_F1 random rows, L2 ~250cyc) is register-prefetched one
// centroid ahead, hidden behind layer-2/3 compute.  (UNCHANGED from R12.)
// ---------------------------------------------------------------------------
__global__ __launch_bounds__(256, 2)
void k_mlp(const float* __restrict__ xyz,
           const float* __restrict__ W1, const float* __restrict__ W2,
           const float* __restrict__ b2, const float* __restrict__ W3,
           const float* __restrict__ b3, float* __restrict__ outf) {
    extern __shared__ float sm[];
    float* sW2  = sm;            // 64*64
    float* sW3  = sm + 4096;     // 64*128
    float* sW1x = sm + 12288;    // 3*64
    float* sb2  = sm + 12480;    // 64
    float* sb3  = sm + 12544;    // 128
    float* hbuf = sm + 12672;    // 2 halves x (h1T 2048 + h2T 2048)
    int tid  = threadIdx.x;
    int ht   = tid & 127;        // thread-in-half
    int half = tid >> 7;

    float* h1T = hbuf + half * 4096;        // [k][n] 64x32
    float* h2T = h1T + 2048;                // [k][n] 64x32

    for (int i = tid; i < 4096; i += 256) sW2[i] = W2[i];
    for (int i = tid; i < 8192; i += 256) sW3[i] = W3[i];
    if (tid < 64) { sW1x[tid] = W1[tid]; sW1x[64+tid] = W1[64+tid]; sW1x[128+tid] = W1[128+tid]; }
    if (tid >= 64 && tid < 128) sb2[tid - 64] = b2[tid - 64];
    if (tid >= 128) sb3[tid - 128] = b3[tid - 128];

    int n1 = ht & 31;  int j0 = (ht >> 5) * 16;     // layer 1
    int tr = ht & 7;   int n0 = tr * 4;             // layer 2/3 n-tile
    int tcg = ht >> 3; int c2 = tcg * 4; int c3 = tcg * 8;

    float  p_dx, p_dy, p_dz;
    float4 p_f[4];
    auto prefetch = [&](int cid) {
        int b = cid >> 12, s = cid & (S_ - 1);
        const float* xb = xyz + (size_t)b * N_ * 3;
        int pidx = g_idx[cid * NS_ + n1];
        p_dx = xb[pidx*3+0] - xb[s*3+0];
        p_dy = xb[pidx*3+1] - xb[s*3+1];
        p_dz = xb[pidx*3+2] - xb[s*3+2];
        const float* f1p = g_F1 + ((size_t)b * N_ + pidx) * 64 + j0;
#pragma unroll
        for (int q = 0; q < 4; q++) p_f[q] = *(const float4*)(f1p + q*4);
    };

    int cid0 = blockIdx.x * 4 + half;
    prefetch(cid0);
    __syncthreads();

    for (int ci = 0; ci < 2; ci++) {
        int cid = cid0 + ci * 2;
        int b = cid >> 12, s = cid & (S_ - 1);

        // ---- layer 1: consume prefetched gather ----
#pragma unroll
        for (int q = 0; q < 4; q++) {
            float4 f = p_f[q];
            int j = j0 + q*4;
            h1T[(j+0)*32+n1] = fmaxf(f.x + p_dx*sW1x[j+0] + p_dy*sW1x[64+j+0] + p_dz*sW1x[128+j+0], 0.f);
            h1T[(j+1)*32+n1] = fmaxf(f.y + p_dx*sW1x[j+1] + p_dy*sW1x[64+j+1] + p_dz*sW1x[128+j+1], 0.f);
            h1T[(j+2)*32+n1] = fmaxf(f.z + p_dx*sW1x[j+2] + p_dy*sW1x[64+j+2] + p_dz*sW1x[128+j+2], 0.f);
            h1T[(j+3)*32+n1] = fmaxf(f.w + p_dx*sW1x[j+3] + p_dy*sW1x[64+j+3] + p_dz*sW1x[128+j+3], 0.f);
        }
        if (ci < 1) prefetch(cid + 2);
        __syncthreads();

        // ---- layer 2 ----
        {
            float acc[4][4];
#pragma unroll
            for (int j = 0; j < 4; j++) {
                float bv = sb2[c2 + j];
                acc[0][j]=bv; acc[1][j]=bv; acc[2][j]=bv; acc[3][j]=bv;
            }
#pragma unroll 8
            for (int k = 0; k < 64; k++) {
                float4 a = *(const float4*)(h1T + k*32 + n0);
                float4 w = *(const float4*)(sW2 + k*64 + c2);
                acc[0][0] += a.x*w.x; acc[0][1] += a.x*w.y; acc[0][2] += a.x*w.z; acc[0][3] += a.x*w.w;
                acc[1][0] += a.y*w.x; acc[1][1] += a.y*w.y; acc[1][2] += a.y*w.z; acc[1][3] += a.y*w.w;
                acc[2][0] += a.z*w.x; acc[2][1] += a.z*w.y; acc[2][2] += a.z*w.z; acc[2][3] += a.z*w.w;
                acc[3][0] += a.w*w.x; acc[3][1] += a.w*w.y; acc[3][2] += a.w*w.z; acc[3][3] += a.w*w.w;
            }
#pragma unroll
            for (int j = 0; j < 4; j++) {
                float4 v = make_float4(fmaxf(acc[0][j],0.f), fmaxf(acc[1][j],0.f),
                                       fmaxf(acc[2][j],0.f), fmaxf(acc[3][j],0.f));
                *(float4*)(h2T + (c2+j)*32 + n0) = v;
            }
        }
        __syncthreads();

        // ---- layer 3 + relu + max over neighbors ----
        {
            float acc[4][8];
#pragma unroll
            for (int j = 0; j < 8; j++) {
                float bv = sb3[c3 + j];
                acc[0][j]=bv; acc[1][j]=bv; acc[2][j]=bv; acc[3][j]=bv;
            }
#pragma unroll 8
            for (int k = 0; k < 64; k++) {
                float4 a  = *(const float4*)(h2T + k*32 + n0);
                float4 w0 = *(const float4*)(sW3 + k*128 + c3);
                float4 w1 = *(const float4*)(sW3 + k*128 + c3 + 4);
                acc[0][0]+=a.x*w0.x; acc[0][1]+=a.x*w0.y; acc[0][2]+=a.x*w0.z; acc[0][3]+=a.x*w0.w;
                acc[0][4]+=a.x*w1.x; acc[0][5]+=a.x*w1.y; acc[0][6]+=a.x*w1.z; acc[0][7]+=a.x*w1.w;
                acc[1][0]+=a.y*w0.x; acc[1][1]+=a.y*w0.y; acc[1][2]+=a.y*w0.z; acc[1][3]+=a.y*w0.w;
                acc[1][4]+=a.y*w1.x; acc[1][5]+=a.y*w1.y; acc[1][6]+=a.y*w1.z; acc[1][7]+=a.y*w1.w;
                acc[2][0]+=a.z*w0.x; acc[2][1]+=a.z*w0.y; acc[2][2]+=a.z*w0.z; acc[2][3]+=a.z*w0.w;
                acc[2][4]+=a.z*w1.x; acc[2][5]+=a.z*w1.y; acc[2][6]+=a.z*w1.z; acc[2][7]+=a.z*w1.w;
                acc[3][0]+=a.w*w0.x; acc[3][1]+=a.w*w0.y; acc[3][2]+=a.w*w0.z; acc[3][3]+=a.w*w0.w;
                acc[3][4]+=a.w*w1.x; acc[3][5]+=a.w*w1.y; acc[3][6]+=a.w*w1.z; acc[3][7]+=a.w*w1.w;
            }
            float m[8];
#pragma unroll
            for (int j = 0; j < 8; j++)
                m[j] = fmaxf(fmaxf(fmaxf(acc[0][j], acc[1][j]),
                                   fmaxf(acc[2][j], acc[3][j])), 0.f);
#pragma unroll
            for (int off = 1; off < 8; off <<= 1) {
#pragma unroll
                for (int j = 0; j < 8; j++)
                    m[j] = fmaxf(m[j], __shfl_xor_sync(0xffffffffu, m[j], off));
            }
            if (tr == 0) {
                float* o = outf + ((size_t)b * 128 + c3) * S_ + s;
#pragma unroll
                for (int j = 0; j < 8; j++) o[(size_t)j * S_] = m[j];
            }
        }
        __syncthreads();
    }
}

// ---------------------------------------------------------------------------
extern "C" void kernel_launch(void* const* d_in, const int* in_sizes, int n_in,
                              void* d_out, int out_size) {
    const float* xyz   = (const float*)d_in[0];
    const float* feats = (const float*)d_in[1];
    const float* W1    = (const float*)d_in[2];
    const float* b1    = (const float*)d_in[3];
    const float* W2    = (const float*)d_in[4];
    const float* b2    = (const float*)d_in[5];
    const float* W3    = (const float*)d_in[6];
    const float* b3    = (const float*)d_in[7];
    float* out = (float*)d_out;

    const int NXYZ = B_ * S_ * 3;               // 24576
    const int NFEA = B_ * 128 * S_;             // 1048576
    float* outf = out + NXYZ;                   // features region (full tuple layout)
    bool full_layout = (out_size >= NXYZ + NFEA + B_ * S_);
    if (!full_layout && out_size == NFEA) outf = out;  // features-only fallback

    const size_t smem_mlp = 20864 * sizeof(float);  // 83456 B
    cudaFuncSetAttribute(k_mlp, cudaFuncAttributeMaxDynamicSharedMemorySize,
                         (int)smem_mlp);

    k_pack_out<<<(B_*N_)/256, 256>>>(xyz, out, full_layout ? 1 : 0);
    k_bq<<<NCID/8, 256>>>(xyz);
    k_f1<<<dim3(N_/64, B_), 256>>>(feats, W1, b1);
    k_mlp<<<NCID/4, 256, smem_mlp>>>(xyz, W1, W2, b2, W3, b3, outf);
}

// round 16
// speedup vs baseline: 1.3307x; 1.0263x over previous
#include <cuda_runtime.h>
#include <cstdint>

// Problem constants (fixed shapes per reference)
#define B_   2
#define N_   16384
#define S_   4096        // npoint
#define C_   64
#define NS_  32          // nsample
#define NCID (B_*S_)     // 8192 centroids total

// Scratch (static __device__ arrays: allocation-free per harness rules)
__device__ float  g_F1[(size_t)B_ * N_ * 64];  // feats@W1[3:] + b1, [b][n][64] (8MB)
__device__ float4 g_pts[(size_t)B_ * N_];      // packed (x,y,z,|p|^2)          (512KB)

// ---------------------------------------------------------------------------
// Kernel 0: pack points to float4 (x,y,z,n2) + new_xyz copy + samp_idx.
// ---------------------------------------------------------------------------
__global__ void k_pack_out(const float* __restrict__ xyz,
                           float* __restrict__ out, int full_layout) {
    int i = blockIdx.x * blockDim.x + threadIdx.x;   // 0 .. 32767
    {
        int b = i >> 14, n = i & (N_ - 1);
        const float* p = xyz + ((size_t)b * N_ + n) * 3;
        float x = p[0], y = p[1], z = p[2];
        g_pts[(size_t)b * N_ + n] = make_float4(x, y, z, x*x + y*y + z*z);
    }
    if (full_layout) {
        if (i < B_ * S_ * 3) {
            int b = i / (S_ * 3), r = i % (S_ * 3);
            out[i] = xyz[(size_t)b * N_ * 3 + r];
        } else {
            int j = i - B_ * S_ * 3;                 // 0 .. 8191
            out[B_*S_*3 + (size_t)B_*128*S_ + j] = (float)(j & (S_ - 1));
        }
    }
}

// ---------------------------------------------------------------------------
// Kernel 1: F1[b][n][j] = sum_c feats[b][c][n] * W1[3+c][j] + b1[j]
// ---------------------------------------------------------------------------
__global__ void k_f1(const float* __restrict__ feats,
                     const float* __restrict__ W1,
                     const float* __restrict__ b1) {
    __shared__ float sF[64 * 64];   // [c][n_local]
    __shared__ float sW[64 * 64];   // [c][j]
    __shared__ float sb[64];
    int b  = blockIdx.y;
    int n0 = blockIdx.x * 64;
    int tid = threadIdx.x;

    for (int i = tid; i < 4096; i += 256) sW[i] = W1[192 + i];  // rows 3..66
    if (tid < 64) sb[tid] = b1[tid];
    const float* fb = feats + (size_t)b * 64 * N_;
    for (int i = tid; i < 4096; i += 256) {
        int c = i >> 6, nn = i & 63;
        sF[c * 64 + nn] = fb[(size_t)c * N_ + n0 + nn];
    }
    __syncthreads();

    int n  = tid & 63;
    int j0 = (tid >> 6) * 16;       // warp-uniform
    float acc[16];
#pragma unroll
    for (int j = 0; j < 16; j++) acc[j] = sb[j0 + j];
#pragma unroll 8
    for (int c = 0; c < 64; c++) {
        float f = sF[c * 64 + n];
        const float4* wp = (const float4*)(sW + c * 64 + j0);
        float4 w0 = wp[0], w1 = wp[1], w2 = wp[2], w3 = wp[3];
        acc[0]  += f*w0.x; acc[1]  += f*w0.y; acc[2]  += f*w0.z; acc[3]  += f*w0.w;
        acc[4]  += f*w1.x; acc[5]  += f*w1.y; acc[6]  += f*w1.z; acc[7]  += f*w1.w;
        acc[8]  += f*w2.x; acc[9]  += f*w2.y; acc[10] += f*w2.z; acc[11] += f*w2.w;
        acc[12] += f*w3.x; acc[13] += f*w3.y; acc[14] += f*w3.z; acc[15] += f*w3.w;
    }
    float* dst = g_F1 + ((size_t)b * N_ + n0 + n) * 64 + j0;
#pragma unroll
    for (int j = 0; j < 16; j += 4) {
        float4 v = make_float4(acc[j], acc[j+1], acc[j+2], acc[j+3]);
        *(float4*)(dst + j) = v;
    }
}

// ---------------------------------------------------------------------------
// Kernel 2: FUSED ball-query + MLP + max-pool.
// Block = 8 centroids, 256 threads.
//   Phase 1: warp w scans g_pts for centroid w (first-32 ascending within
//            radius, first-hit fill) -> indices into smem s_idx. No barriers
//            between warps; direct L1/L2 stream reads, unroll-8 (MLP=8).
//   Phase 2: R12 MLP: 2 halves x 4 centroid-pairs, layer-1 gather prefetched.
// bq's LSU/ballot work overlaps the co-resident block's FMA work.
// ---------------------------------------------------------------------------
__global__ __launch_bounds__(256, 2)
void k_bqmlp(const float* __restrict__ W1, const float* __restrict__ W2,
             const float* __restrict__ b2, const float* __restrict__ W3,
             const float* __restrict__ b3, float* __restrict__ outf) {
    extern __shared__ float sm[];
    float* sW2  = sm;            // 64*64
    float* sW3  = sm + 4096;     // 64*128
    float* sW1x = sm + 12288;    // 3*64
    float* sb2  = sm + 12480;    // 64
    float* sb3  = sm + 12544;    // 128
    float* hbuf = sm + 12672;    // 2 halves x (h1T 2048 + h2T 2048)
    int*   s_idx = (int*)(sm + 20864);  // [8][32] neighbor indices
    int tid  = threadIdx.x;
    int lane = tid & 31, w = tid >> 5;
    int ht   = tid & 127;
    int half = tid >> 7;

    // ---- weight staging (no barrier needed until after phase 1) ----
    for (int i = tid; i < 4096; i += 256) sW2[i] = W2[i];
    for (int i = tid; i < 8192; i += 256) sW3[i] = W3[i];
    if (tid < 64) { sW1x[tid] = W1[tid]; sW1x[64+tid] = W1[64+tid]; sW1x[128+tid] = W1[128+tid]; }
    if (tid >= 64 && tid < 128) sb2[tid - 64] = b2[tid - 64];
    if (tid >= 128 && tid < 256) sb3[tid - 128] = b3[tid - 128];

    // ================= Phase 1: ball query (one warp per centroid) =========
    {
        int cid = blockIdx.x * 8 + w;
        int b = cid >> 12, s = cid & (S_ - 1);
        const float4* pb = g_pts + (size_t)b * N_;
        float4 cp = pb[s];
        float cx = cp.x, cy = cp.y, cz = cp.z, cn2 = cp.w;
        const float R2 = 0.4f * 0.4f;

        int  cnt = 0, firstn = 0;
        int* myidx = s_idx + w * NS_;

        for (int t0 = 0; t0 < N_; t0 += 256) {
            // load 8 groups of 32 points (independent LDG.128s, MLP=8)
            float4 p[8];
#pragma unroll
            for (int q = 0; q < 8; q++) p[q] = pb[t0 + q*32 + lane];
            unsigned hm[8];
#pragma unroll
            for (int q = 0; q < 8; q++) {
                float d2 = cn2 + p[q].w - 2.0f*(cx*p[q].x + cy*p[q].y + cz*p[q].z);
                hm[q] = __ballot_sync(0xffffffffu, d2 < R2);
            }
#pragma unroll
            for (int q = 0; q < 8; q++) {
                unsigned mask = hm[q];
                if (mask) {
                    if (cnt == 0) firstn = t0 + q*32 + (__ffs(mask) - 1);
                    bool hit = (mask >> lane) & 1u;
                    int pos = cnt + __popc(mask & ((1u << lane) - 1u));
                    if (hit && pos < NS_) myidx[pos] = t0 + q*32 + lane;
                    cnt += __popc(mask);
                }
            }
            if (cnt >= NS_) break;
        }
        if (cnt < NS_) {
            int fv = (cnt > 0) ? firstn : 0;
            if (lane < NS_ - cnt) myidx[cnt + lane] = fv;
        }
    }
    __syncthreads();   // s_idx + weights visible to all

    // ================= Phase 2: MLP + max-pool (R12 structure) =============
    float* h1T = hbuf + half * 4096;        // [k][n] 64x32
    float* h2T = h1T + 2048;                // [k][n] 64x32

    int n1 = ht & 31;  int j0 = (ht >> 5) * 16;     // layer 1
    int tr = ht & 7;   int n0 = tr * 4;             // layer 2/3 n-tile
    int tcg = ht >> 3; int c2 = tcg * 4; int c3 = tcg * 8;

    float  p_dx, p_dy, p_dz;
    float4 p_f[4];
    auto prefetch = [&](int lc) {                   // lc = local centroid 0..7
        int cid = blockIdx.x * 8 + lc;
        int b = cid >> 12, s = cid & (S_ - 1);
        int pidx = s_idx[lc * NS_ + n1];
        float4 pp = g_pts[(size_t)b * N_ + pidx];
        float4 pc = g_pts[(size_t)b * N_ + s];
        p_dx = pp.x - pc.x; p_dy = pp.y - pc.y; p_dz = pp.z - pc.z;
        const float* f1p = g_F1 + ((size_t)b * N_ + pidx) * 64 + j0;
#pragma unroll
        for (int q = 0; q < 4; q++) p_f[q] = *(const float4*)(f1p + q*4);
    };

    prefetch(half);

    for (int ci = 0; ci < 4; ci++) {
        int lc  = half + ci * 2;
        int cid = blockIdx.x * 8 + lc;
        int b = cid >> 12, s = cid & (S_ - 1);

        // ---- layer 1: consume prefetched gather ----
#pragma unroll
        for (int q = 0; q < 4; q++) {
            float4 f = p_f[q];
            int j = j0 + q*4;
            h1T[(j+0)*32+n1] = fmaxf(f.x + p_dx*sW1x[j+0] + p_dy*sW1x[64+j+0] + p_dz*sW1x[128+j+0], 0.f);
            h1T[(j+1)*32+n1] = fmaxf(f.y + p_dx*sW1x[j+1] + p_dy*sW1x[64+j+1] + p_dz*sW1x[128+j+1], 0.f);
            h1T[(j+2)*32+n1] = fmaxf(f.z + p_dx*sW1x[j+2] + p_dy*sW1x[64+j+2] + p_dz*sW1x[128+j+2], 0.f);
            h1T[(j+3)*32+n1] = fmaxf(f.w + p_dx*sW1x[j+3] + p_dy*sW1x[64+j+3] + p_dz*sW1x[128+j+3], 0.f);
        }
        if (ci < 3) prefetch(lc + 2);   // hide next gather behind layers 2+3
        __syncthreads();

        // ---- layer 2 ----
        {
            float acc[4][4];
#pragma unroll
            for (int j = 0; j < 4; j++) {
                float bv = sb2[c2 + j];
                acc[0][j]=bv; acc[1][j]=bv; acc[2][j]=bv; acc[3][j]=bv;
            }
#pragma unroll 8
            for (int k = 0; k < 64; k++) {
                float4 a = *(const float4*)(h1T + k*32 + n0);
                float4 ww = *(const float4*)(sW2 + k*64 + c2);
                acc[0][0] += a.x*ww.x; acc[0][1] += a.x*ww.y; acc[0][2] += a.x*ww.z; acc[0][3] += a.x*ww.w;
                acc[1][0] += a.y*ww.x; acc[1][1] += a.y*ww.y; acc[1][2] += a.y*ww.z; acc[1][3] += a.y*ww.w;
                acc[2][0] += a.z*ww.x; acc[2][1] += a.z*ww.y; acc[2][2] += a.z*ww.z; acc[2][3] += a.z*ww.w;
                acc[3][0] += a.w*ww.x; acc[3][1] += a.w*ww.y; acc[3][2] += a.w*ww.z; acc[3][3] += a.w*ww.w;
            }
#pragma unroll
            for (int j = 0; j < 4; j++) {
                float4 v = make_float4(fmaxf(acc[0][j],0.f), fmaxf(acc[1][j],0.f),
                                       fmaxf(acc[2][j],0.f), fmaxf(acc[3][j],0.f));
                *(float4*)(h2T + (c2+j)*32 + n0) = v;
            }
        }
        __syncthreads();

        // ---- layer 3 + relu + max over neighbors ----
        {
            float acc[4][8];
#pragma unroll
            for (int j = 0; j < 8; j++) {
                float bv = sb3[c3 + j];
                acc[0][j]=bv; acc[1][j]=bv; acc[2][j]=bv; acc[3][j]=bv;
            }
#pragma unroll 8
            for (int k = 0; k < 64; k++) {
                float4 a  = *(const float4*)(h2T + k*32 + n0);
                float4 w0 = *(const float4*)(sW3 + k*128 + c3);
                float4 w1 = *(const float4*)(sW3 + k*128 + c3 + 4);
                acc[0][0]+=a.x*w0.x; acc[0][1]+=a.x*w0.y; acc[0][2]+=a.x*w0.z; acc[0][3]+=a.x*w0.w;
                acc[0][4]+=a.x*w1.x; acc[0][5]+=a.x*w1.y; acc[0][6]+=a.x*w1.z; acc[0][7]+=a.x*w1.w;
                acc[1][0]+=a.y*w0.x; acc[1][1]+=a.y*w0.y; acc[1][2]+=a.y*w0.z; acc[1][3]+=a.y*w0.w;
                acc[1][4]+=a.y*w1.x; acc[1][5]+=a.y*w1.y; acc[1][6]+=a.y*w1.z; acc[1][7]+=a.y*w1.w;
                acc[2][0]+=a.z*w0.x; acc[2][1]+=a.z*w0.y; acc[2][2]+=a.z*w0.z; acc[2][3]+=a.z*w0.w;
                acc[2][4]+=a.z*w1.x; acc[2][5]+=a.z*w1.y; acc[2][6]+=a.z*w1.z; acc[2][7]+=a.z*w1.w;
                acc[3][0]+=a.w*w0.x; acc[3][1]+=a.w*w0.y; acc[3][2]+=a.w*w0.z; acc[3][3]+=a.w*w0.w;
                acc[3][4]+=a.w*w1.x; acc[3][5]+=a.w*w1.y; acc[3][6]+=a.w*w1.z; acc[3][7]+=a.w*w1.w;
            }
            float m[8];
#pragma unroll
            for (int j = 0; j < 8; j++)
                m[j] = fmaxf(fmaxf(fmaxf(acc[0][j], acc[1][j]),
                                   fmaxf(acc[2][j], acc[3][j])), 0.f);
#pragma unroll
            for (int off = 1; off < 8; off <<= 1) {
#pragma unroll
                for (int j = 0; j < 8; j++)
                    m[j] = fmaxf(m[j], __shfl_xor_sync(0xffffffffu, m[j], off));
            }
            if (tr == 0) {
                float* o = outf + ((size_t)b * 128 + c3) * S_ + s;
#pragma unroll
                for (int j = 0; j < 8; j++) o[(size_t)j * S_] = m[j];
            }
        }
        __syncthreads();
    }
}

// ---------------------------------------------------------------------------
extern "C" void kernel_launch(void* const* d_in, const int* in_sizes, int n_in,
                              void* d_out, int out_size) {
    const float* xyz   = (const float*)d_in[0];
    const float* feats = (const float*)d_in[1];
    const float* W1    = (const float*)d_in[2];
    const float* b1    = (const float*)d_in[3];
    const float* W2    = (const float*)d_in[4];
    const float* b2    = (const float*)d_in[5];
    const float* W3    = (const float*)d_in[6];
    const float* b3    = (const float*)d_in[7];
    float* out = (float*)d_out;

    const int NXYZ = B_ * S_ * 3;               // 24576
    const int NFEA = B_ * 128 * S_;             // 1048576
    float* outf = out + NXYZ;                   // features region (full tuple layout)
    bool full_layout = (out_size >= NXYZ + NFEA + B_ * S_);
    if (!full_layout && out_size == NFEA) outf = out;  // features-only fallback

    const size_t smem_fused = 20864 * sizeof(float) + 8 * NS_ * sizeof(int); // 84480 B
    cudaFuncSetAttribute(k_bqmlp, cudaFuncAttributeMaxDynamicSharedMemorySize,
                         (int)smem_fused);

    k_pack_out<<<(B_*N_)/256, 256>>>(xyz, out, full_layout ? 1 : 0);
    k_f1<<<dim3(N_/64, B_), 256>>>(feats, W1, b1);
    k_bqmlp<<<NCID/8, 256, smem_fused>>>(W1, W2, b2, W3, b3, outf);
}